// round 3
// baseline (speedup 1.0000x reference)
#include <cuda_runtime.h>
#include <cuda_bf16.h>

// Problem constants
#define NGROUPS 8
#define CIN 4
#define COUT 4
#define KSIZE 5
#define NPART 8
#define B_    8
#define H_    256
#define W_    512
#define CI_   32
#define CO_   32
#define HP_   32      // H_/NPART rows per slab

// Tile config
#define TX 64         // output cols per block (two 32-col halves, paired)
#define TY 4          // output rows per block
#define NTHREADS 256  // 32 co * 8 xsub; each thread: 4 col-pairs x 4 rows

#define NTAPS 13
#define SIN_ROWS 6            // TY + 2
#define SIN_WCOLS 36          // pair-words per row: covers scalar cols [-2, 66)
#define SIN_WORDS (CI_ * SIN_ROWS * SIN_WCOLS)      // 6912 x u64
#define SW_ELEMS  (CI_ * NTAPS * CO_)               // 13312 floats
#define SMEM_BYTES (SIN_WORDS * 8 + SW_ELEMS * 4)   // 108544

typedef unsigned long long u64;

__device__ __forceinline__ u64 pack2(float lo, float hi) {
    u64 r; asm("mov.b64 %0, {%1, %2};" : "=l"(r) : "f"(lo), "f"(hi)); return r;
}
__device__ __forceinline__ void unpack2(u64 v, float& lo, float& hi) {
    asm("mov.b64 {%0, %1}, %2;" : "=f"(lo), "=f"(hi) : "l"(v));
}
__device__ __forceinline__ void ffma2(u64& d, u64 a, u64 b) {
    asm("fma.rn.f32x2 %0, %1, %2, %0;" : "+l"(d) : "l"(a), "l"(b));
}

// Masked-weight scratch: layout [ci][tap][co]
__device__ float g_w[SW_ELEMS];

// ---------------------------------------------------------------------------
// Prep: apply PixelCNN group mask (HIDDEN: center visible iff gin<=gout),
// reorder weights to [ci][tap][co].
// tap 0..9 -> ky=tap/5, kx=tap%5 ; tap 10,11 -> ky=2,kx=0,1 ; tap 12 -> center
// ---------------------------------------------------------------------------
__global__ void prep_weights(const float* __restrict__ w) {
    int i = blockIdx.x * blockDim.x + threadIdx.x;
    if (i >= SW_ELEMS) return;
    int co = i & 31;
    int k  = (i >> 5) % NTAPS;
    int ci = i / (NTAPS * CO_);
    int ky, kx;
    float m = 1.0f;
    if (k < 10)      { ky = k / 5; kx = k % 5; }
    else if (k == 10){ ky = 2; kx = 0; }
    else if (k == 11){ ky = 2; kx = 1; }
    else             { ky = 2; kx = 2; m = ((ci >> 2) <= (co >> 2)) ? 1.0f : 0.0f; }
    g_w[i] = w[((co * CI_ + ci) * KSIZE + ky) * KSIZE + kx] * m;
}

// ---------------------------------------------------------------------------
// Main conv kernel. Grid: (W/TX=8, HP/TY=8, B*NPART=64). Block: 256 threads.
// Input staged as interleaved pairs: word pc of row = {x[x0-2+pc], x[x0+30+pc]}
// so every tap's f32x2 operand is an aligned 64-bit smem word.
// ---------------------------------------------------------------------------
extern __shared__ char smem_raw[];

__global__ void __launch_bounds__(NTHREADS, 2)
conv_kernel(const float* __restrict__ x,
            const float* __restrict__ bias,
            const float* __restrict__ alpha,
            const int*   __restrict__ widths,
            float* __restrict__ out)
{
    const int tile_x = blockIdx.x;
    const int tile_y = blockIdx.y;
    const int slab   = blockIdx.z;
    const int b      = slab >> 3;
    const int part   = slab & 7;
    const int width  = widths[part];
    const int x0     = tile_x * TX;
    const int y0     = tile_y * TY;          // local row in slab
    const int gy0    = part * HP_ + y0;      // global row

    const int t    = threadIdx.x;
    const int xsub = t & 7;
    const int co   = t >> 3;
    const int cs   = xsub * 4;               // first col-pair index of this thread

    // ---- fast path: whole tile past the valid width -> zeros ----
    if (x0 >= width) {
        const float4 z = make_float4(0.f, 0.f, 0.f, 0.f);
        #pragma unroll
        for (int o = 0; o < TY; ++o) {
            int base = ((b * CO_ + co) * H_ + gy0 + o) * W_ + x0 + cs;
            *(float4*)(out + base)      = z;
            *(float4*)(out + base + 32) = z;
        }
        return;
    }

    u64*   sIn = (u64*)smem_raw;                     // [ci][6][36] pair-words
    float* sW  = (float*)(smem_raw + SIN_WORDS * 8); // [ci][13][co]

    // ---- stage weights ----
    #pragma unroll
    for (int i = t; i < SW_ELEMS; i += NTHREADS) sW[i] = g_w[i];

    // ---- stage input tile as interleaved (c, c+32) pairs, masked ----
    const int wlim = (width < W_) ? width : W_;
    for (int i = t; i < SIN_WORDS; i += NTHREADS) {
        int pc = i % SIN_WCOLS;
        int rr = i / SIN_WCOLS;
        int r  = rr % SIN_ROWS;
        int ci = rr / SIN_ROWS;
        int ly = y0 - 2 + r;                 // local row in slab (pad outside)
        float v0 = 0.f, v1 = 0.f;
        if (ly >= 0 && ly < HP_) {
            const float* row = x + ((b * CI_ + ci) * H_ + part * HP_ + ly) * W_;
            int g0 = x0 - 2 + pc;
            int g1 = x0 + 30 + pc;
            if (g0 >= 0 && g0 < wlim) v0 = row[g0];
            if (g1 < wlim)            v1 = row[g1];
        }
        sIn[i] = pack2(v0, v1);
    }
    __syncthreads();

    u64 acc[TY][4];
    #pragma unroll
    for (int o = 0; o < TY; ++o)
        #pragma unroll
        for (int j = 0; j < 4; ++j) acc[o][j] = 0ull;

    #pragma unroll 1
    for (int ci = 0; ci < CI_; ++ci) {
        // splat weights {w,w} once per ci
        u64 wp[NTAPS];
        const float* wrow = sW + ci * (NTAPS * CO_) + co;
        #pragma unroll
        for (int k = 0; k < NTAPS; ++k) {
            float wv = wrow[k * CO_];
            wp[k] = pack2(wv, wv);
        }

        const u64* base = sIn + ci * (SIN_ROWS * SIN_WCOLS) + cs;
        #pragma unroll
        for (int r = 0; r < SIN_ROWS; ++r) {
            u64 p[8];
            const ulonglong2* q = (const ulonglong2*)(base + r * SIN_WCOLS);
            ulonglong2 q0 = q[0], q1 = q[1], q2 = q[2], q3 = q[3];
            p[0]=q0.x; p[1]=q0.y; p[2]=q1.x; p[3]=q1.y;
            p[4]=q2.x; p[5]=q2.y; p[6]=q3.x; p[7]=q3.y;

            if (r < TY) {                         // ky=0 taps -> out row r
                #pragma unroll
                for (int kx = 0; kx < 5; ++kx)
                    #pragma unroll
                    for (int j = 0; j < 4; ++j)
                        ffma2(acc[r][j], p[j + kx], wp[kx]);
            }
            if (r >= 1 && r < TY + 1) {           // ky=1 taps -> out row r-1
                #pragma unroll
                for (int kx = 0; kx < 5; ++kx)
                    #pragma unroll
                    for (int j = 0; j < 4; ++j)
                        ffma2(acc[r-1][j], p[j + kx], wp[5 + kx]);
            }
            if (r >= 2) {                         // ky=2 taps (kx 0..2) -> r-2
                #pragma unroll
                for (int kx = 0; kx < 3; ++kx)
                    #pragma unroll
                    for (int j = 0; j < 4; ++j)
                        ffma2(acc[r-2][j], p[j + kx], wp[10 + kx]);
            }
        }
    }

    // ---- epilogue: bias, leaky-ReLU, width mask, vectorized store ----
    const float bz = __ldg(bias  + co);
    const float al = __ldg(alpha + co);
    const int c_lo = x0 + cs;
    #pragma unroll
    for (int o = 0; o < TY; ++o) {
        float lo[4], hi[4];
        #pragma unroll
        for (int j = 0; j < 4; ++j) {
            float yl, yh;
            unpack2(acc[o][j], yl, yh);
            yl += bz; yh += bz;
            yl = (yl > 0.f) ? yl : al * yl;
            yh = (yh > 0.f) ? yh : al * yh;
            lo[j] = (c_lo + j      < width) ? yl : 0.f;
            hi[j] = (c_lo + 32 + j < width) ? yh : 0.f;
        }
        int base = ((b * CO_ + co) * H_ + gy0 + o) * W_ + c_lo;
        *(float4*)(out + base)      = make_float4(lo[0], lo[1], lo[2], lo[3]);
        *(float4*)(out + base + 32) = make_float4(hi[0], hi[1], hi[2], hi[3]);
    }
}

// ---------------------------------------------------------------------------
// Launch
// ---------------------------------------------------------------------------
extern "C" void kernel_launch(void* const* d_in, const int* in_sizes, int n_in,
                              void* d_out, int out_size)
{
    const float* x      = (const float*)d_in[0];
    const float* weight = (const float*)d_in[1];
    const float* bias   = (const float*)d_in[2];
    const float* alpha  = (const float*)d_in[3];
    const int*   widths = (const int*)  d_in[4];
    float* out = (float*)d_out;

    (void)in_sizes; (void)n_in; (void)out_size;

    cudaFuncSetAttribute(conv_kernel,
                         cudaFuncAttributeMaxDynamicSharedMemorySize,
                         SMEM_BYTES);

    prep_weights<<<(SW_ELEMS + 255) / 256, 256>>>(weight);

    dim3 grid(W_ / TX, HP_ / TY, B_ * NPART);
    conv_kernel<<<grid, NTHREADS, SMEM_BYTES>>>(x, bias, alpha, widths, out);
}

// round 4
// speedup vs baseline: 1.1877x; 1.1877x over previous
#include <cuda_runtime.h>
#include <cuda_bf16.h>

// Problem constants
#define NGROUPS 8
#define CIN 4
#define COUT 4
#define KSIZE 5
#define NPART 8
#define B_    8
#define H_    256
#define W_    512
#define CI_   32
#define CO_   32
#define HP_   32      // H_/NPART rows per slab

// Tile config
#define TX 64         // output cols per block
#define TY 4          // output rows per block
#define XS 8          // cols per thread
#define NTHREADS 256  // 32 co * 8 xsub

#define NTAPS 13
#define SIN_ROWS 6            // TY + 2
#define SIN_COLS 68           // TX + 4
#define SIN_ELEMS (CI_ * SIN_ROWS * SIN_COLS)       // 13056
#define SW_ELEMS  (CI_ * NTAPS * CO_)               // 13312
#define SMEM_BYTES (SIN_ELEMS * 4)                  // 52224 -> 3 blocks/SM

// Masked-weight scratch in global: layout [ci][tap][co]
__device__ float g_w[SW_ELEMS];

// ---------------------------------------------------------------------------
// Prep: apply PixelCNN group mask (HIDDEN: center visible iff gin<=gout),
// reorder weights to [ci][tap][co].
// tap 0..9 -> ky=tap/5, kx=tap%5 ; tap 10,11 -> ky=2,kx=0,1 ; tap 12 -> center
// ---------------------------------------------------------------------------
__global__ void prep_weights(const float* __restrict__ w) {
    int i = blockIdx.x * blockDim.x + threadIdx.x;
    if (i >= SW_ELEMS) return;
    int co = i & 31;
    int k  = (i >> 5) % NTAPS;
    int ci = i / (NTAPS * CO_);
    int ky, kx;
    float m = 1.0f;
    if (k < 10)      { ky = k / 5; kx = k % 5; }
    else if (k == 10){ ky = 2; kx = 0; }
    else if (k == 11){ ky = 2; kx = 1; }
    else             { ky = 2; kx = 2; m = ((ci >> 2) <= (co >> 2)) ? 1.0f : 0.0f; }
    g_w[i] = w[((co * CI_ + ci) * KSIZE + ky) * KSIZE + kx] * m;
}

// ---------------------------------------------------------------------------
// Main conv kernel. Grid: (W/TX=8, HP/TY=8, B*NPART=64). Block: 256 threads.
// Input staged in smem [ci][6][68]; weights read via __ldg (L1, 16B/warp/tap).
// ---------------------------------------------------------------------------
extern __shared__ float smem[];

__global__ void __launch_bounds__(NTHREADS, 3)
conv_kernel(const float* __restrict__ x,
            const float* __restrict__ bias,
            const float* __restrict__ alpha,
            const int*   __restrict__ widths,
            float* __restrict__ out)
{
    const int tile_x = blockIdx.x;
    const int tile_y = blockIdx.y;
    const int slab   = blockIdx.z;
    const int b      = slab >> 3;
    const int part   = slab & 7;
    const int width  = widths[part];
    const int x0     = tile_x * TX;
    const int y0     = tile_y * TY;          // local row in slab
    const int gy0    = part * HP_ + y0;      // global row

    const int t    = threadIdx.x;
    const int xsub = t & 7;
    const int co   = t >> 3;
    const int xoff = xsub * XS;

    // ---- fast path: whole tile past the valid width -> zeros ----
    if (x0 >= width) {
        const float4 z = make_float4(0.f, 0.f, 0.f, 0.f);
        #pragma unroll
        for (int o = 0; o < TY; ++o) {
            int base = ((b * CO_ + co) * H_ + gy0 + o) * W_ + x0 + xoff;
            *(float4*)(out + base)     = z;
            *(float4*)(out + base + 4) = z;
        }
        return;
    }

    float* sIn = smem;                 // [ci][6][68]

    // ---- stage input tile (masked). Warp w stages ci in [4w, 4w+4).
    //      No integer div/mod: rr -> (ci_off = rr/6, r = rr%6) fold at
    //      compile time under full unroll. Coalesced global reads. ----
    {
        const int warp = t >> 5;
        const int lane = t & 31;
        const int wlim = (width < W_) ? width : W_;
        const int ci0  = warp * 4;
        const float* xb = x + ((size_t)(b * CI_ + ci0) * H_ + part * HP_) * W_;
        float* sb = sIn + ci0 * (SIN_ROWS * SIN_COLS);
        #pragma unroll
        for (int rr = 0; rr < 24; ++rr) {
            const int cio = rr / 6;          // compile-time
            const int r   = rr % 6;          // compile-time
            const int ly  = y0 - 2 + r;      // local row in slab
            const float* grow = xb + (size_t)cio * H_ * W_ + ly * W_;
            float* srow = sb + (cio * SIN_ROWS + r) * SIN_COLS;
            const bool rowok = (ly >= 0) && (ly < HP_);
            // cols: lane, lane+32, and lanes 0..3 cover col 64..67
            int g0 = x0 - 2 + lane;
            int g1 = g0 + 32;
            float v0 = 0.f, v1 = 0.f;
            if (rowok) {
                if (g0 >= 0 && g0 < wlim) v0 = grow[g0];
                if (g1 < wlim)            v1 = grow[g1];
            }
            srow[lane]      = v0;
            srow[lane + 32] = v1;
            if (lane < 4) {
                int g2 = g0 + 64;
                float v2 = (rowok && g2 < wlim) ? grow[g2] : 0.f;
                srow[lane + 64] = v2;
            }
        }
    }
    __syncthreads();

    float acc[TY][XS];
    #pragma unroll
    for (int o = 0; o < TY; ++o)
        #pragma unroll
        for (int j = 0; j < XS; ++j) acc[o][j] = 0.f;

    const float* wbase = g_w + co;

    #pragma unroll 1
    for (int ci = 0; ci < CI_; ++ci) {
        float wgt[NTAPS];
        const float* wp = wbase + ci * (NTAPS * CO_);
        #pragma unroll
        for (int k = 0; k < NTAPS; ++k) wgt[k] = __ldg(wp + k * CO_);

        const float* rb = sIn + ci * (SIN_ROWS * SIN_COLS) + xoff;
        #pragma unroll
        for (int r = 0; r < SIN_ROWS; ++r) {
            float v[12];
            const float4 a0 = *(const float4*)(rb + r * SIN_COLS);
            const float4 a1 = *(const float4*)(rb + r * SIN_COLS + 4);
            const float4 a2 = *(const float4*)(rb + r * SIN_COLS + 8);
            v[0]=a0.x; v[1]=a0.y; v[2]=a0.z; v[3]=a0.w;
            v[4]=a1.x; v[5]=a1.y; v[6]=a1.z; v[7]=a1.w;
            v[8]=a2.x; v[9]=a2.y; v[10]=a2.z; v[11]=a2.w;

            // out row o uses input rows o (ky0), o+1 (ky1), o+2 (ky2)
            if (r < TY) {                         // ky=0 taps for out row r
                #pragma unroll
                for (int kx = 0; kx < 5; ++kx)
                    #pragma unroll
                    for (int j = 0; j < XS; ++j)
                        acc[r][j] = fmaf(v[j + kx], wgt[kx], acc[r][j]);
            }
            if (r >= 1 && r < TY + 1) {           // ky=1 taps for out row r-1
                #pragma unroll
                for (int kx = 0; kx < 5; ++kx)
                    #pragma unroll
                    for (int j = 0; j < XS; ++j)
                        acc[r-1][j] = fmaf(v[j + kx], wgt[5 + kx], acc[r-1][j]);
            }
            if (r >= 2) {                         // ky=2 taps (kx 0..2) -> r-2
                #pragma unroll
                for (int j = 0; j < XS; ++j) {
                    acc[r-2][j] = fmaf(v[j],     wgt[10], acc[r-2][j]);
                    acc[r-2][j] = fmaf(v[j + 1], wgt[11], acc[r-2][j]);
                    acc[r-2][j] = fmaf(v[j + 2], wgt[12], acc[r-2][j]);
                }
            }
        }
    }

    // ---- epilogue: bias, leaky-ReLU, width mask, vectorized store ----
    const float bz = __ldg(bias  + co);
    const float al = __ldg(alpha + co);
    #pragma unroll
    for (int o = 0; o < TY; ++o) {
        float vals[XS];
        #pragma unroll
        for (int j = 0; j < XS; ++j) {
            float y = acc[o][j] + bz;
            y = (y > 0.f) ? y : al * y;
            int gx = x0 + xoff + j;
            vals[j] = (gx < width) ? y : 0.f;
        }
        int base = ((b * CO_ + co) * H_ + gy0 + o) * W_ + x0 + xoff;
        *(float4*)(out + base)     = make_float4(vals[0], vals[1], vals[2], vals[3]);
        *(float4*)(out + base + 4) = make_float4(vals[4], vals[5], vals[6], vals[7]);
    }
}

// ---------------------------------------------------------------------------
// Launch
// ---------------------------------------------------------------------------
extern "C" void kernel_launch(void* const* d_in, const int* in_sizes, int n_in,
                              void* d_out, int out_size)
{
    const float* x      = (const float*)d_in[0];
    const float* weight = (const float*)d_in[1];
    const float* bias   = (const float*)d_in[2];
    const float* alpha  = (const float*)d_in[3];
    const int*   widths = (const int*)  d_in[4];
    float* out = (float*)d_out;

    (void)in_sizes; (void)n_in; (void)out_size;

    cudaFuncSetAttribute(conv_kernel,
                         cudaFuncAttributeMaxDynamicSharedMemorySize,
                         SMEM_BYTES);

    prep_weights<<<(SW_ELEMS + 255) / 256, 256>>>(weight);

    dim3 grid(W_ / TX, HP_ / TY, B_ * NPART);
    conv_kernel<<<grid, NTHREADS, SMEM_BYTES>>>(x, bias, alpha, widths, out);
}

// round 5
// speedup vs baseline: 1.2002x; 1.0105x over previous
#include <cuda_runtime.h>
#include <cuda_bf16.h>

// Problem constants
#define NGROUPS 8
#define CIN 4
#define COUT 4
#define KSIZE 5
#define NPART 8
#define B_    8
#define H_    256
#define W_    512
#define CI_   32
#define CO_   32
#define HP_   32      // H_/NPART rows per slab

// Tile config
#define TX 64         // output cols per block
#define TY 4          // output rows per block
#define XS 8          // cols per thread
#define NTHREADS 256  // 32 co * 8 xsub

#define NTAPS 13
#define SIN_ROWS 6            // TY + 2
#define SIN_COLS 68           // TX + 4
#define SIN_ELEMS (CI_ * SIN_ROWS * SIN_COLS)       // 13056
#define SMEM_BYTES (SIN_ELEMS * 4)                  // 52224 -> 3 blocks/SM

// Masked-weight scratch in global: layout [ci][co][16] (taps padded 13->16)
// so a thread grabs all 13 taps with 3x LDG.128 + 1x LDG.32.
#define WROW 16
__device__ float g_w[CI_ * CO_ * WROW];

// ---------------------------------------------------------------------------
// Prep: apply PixelCNN group mask (HIDDEN: center visible iff gin<=gout),
// reorder weights to [ci][co][16taps].
// tap 0..9 -> ky=tap/5, kx=tap%5 ; tap 10,11 -> ky=2,kx=0,1 ; tap 12 -> center
// ---------------------------------------------------------------------------
__global__ void prep_weights(const float* __restrict__ w) {
    int i = blockIdx.x * blockDim.x + threadIdx.x;
    if (i >= CI_ * CO_ * WROW) return;
    int k  = i & 15;
    int co = (i >> 4) & 31;
    int ci = i >> 9;
    float val = 0.0f;
    if (k < NTAPS) {
        int ky, kx;
        float m = 1.0f;
        if (k < 10)      { ky = k / 5; kx = k % 5; }
        else if (k == 10){ ky = 2; kx = 0; }
        else if (k == 11){ ky = 2; kx = 1; }
        else             { ky = 2; kx = 2; m = ((ci >> 2) <= (co >> 2)) ? 1.0f : 0.0f; }
        val = w[((co * CI_ + ci) * KSIZE + ky) * KSIZE + kx] * m;
    }
    g_w[i] = val;
}

// ---------------------------------------------------------------------------
// Main conv kernel. Grid: (W/TX=8, HP/TY=8, B*NPART=64). Block: 256 threads.
// Input staged in smem [ci][6][68]; weights software-pipelined from global
// (register double-buffer, prefetch distance = one full 416-FMA block).
// ---------------------------------------------------------------------------
extern __shared__ float smem[];

__device__ __forceinline__ void load_w(float* wgt, const float* __restrict__ wp) {
    const float4* q = (const float4*)wp;
    float4 a = __ldg(q);
    float4 b = __ldg(q + 1);
    float4 c = __ldg(q + 2);
    wgt[0]=a.x; wgt[1]=a.y; wgt[2]=a.z;  wgt[3]=a.w;
    wgt[4]=b.x; wgt[5]=b.y; wgt[6]=b.z;  wgt[7]=b.w;
    wgt[8]=c.x; wgt[9]=c.y; wgt[10]=c.z; wgt[11]=c.w;
    wgt[12] = __ldg(wp + 12);
}

__device__ __forceinline__ void fma_block(float acc[TY][XS], const float* rbase,
                                          const float* wgt) {
    #pragma unroll
    for (int r = 0; r < SIN_ROWS; ++r) {
        float v[12];
        const float4 a0 = *(const float4*)(rbase + r * SIN_COLS);
        const float4 a1 = *(const float4*)(rbase + r * SIN_COLS + 4);
        const float4 a2 = *(const float4*)(rbase + r * SIN_COLS + 8);
        v[0]=a0.x; v[1]=a0.y; v[2]=a0.z; v[3]=a0.w;
        v[4]=a1.x; v[5]=a1.y; v[6]=a1.z; v[7]=a1.w;
        v[8]=a2.x; v[9]=a2.y; v[10]=a2.z; v[11]=a2.w;

        // out row o uses input rows o (ky0), o+1 (ky1), o+2 (ky2)
        if (r < TY) {                         // ky=0 taps for out row r
            #pragma unroll
            for (int kx = 0; kx < 5; ++kx)
                #pragma unroll
                for (int j = 0; j < XS; ++j)
                    acc[r][j] = fmaf(v[j + kx], wgt[kx], acc[r][j]);
        }
        if (r >= 1 && r < TY + 1) {           // ky=1 taps for out row r-1
            #pragma unroll
            for (int kx = 0; kx < 5; ++kx)
                #pragma unroll
                for (int j = 0; j < XS; ++j)
                    acc[r-1][j] = fmaf(v[j + kx], wgt[5 + kx], acc[r-1][j]);
        }
        if (r >= 2) {                         // ky=2 taps (kx 0..2) -> r-2
            #pragma unroll
            for (int j = 0; j < XS; ++j) {
                acc[r-2][j] = fmaf(v[j],     wgt[10], acc[r-2][j]);
                acc[r-2][j] = fmaf(v[j + 1], wgt[11], acc[r-2][j]);
                acc[r-2][j] = fmaf(v[j + 2], wgt[12], acc[r-2][j]);
            }
        }
    }
}

__global__ void __launch_bounds__(NTHREADS, 3)
conv_kernel(const float* __restrict__ x,
            const float* __restrict__ bias,
            const float* __restrict__ alpha,
            const int*   __restrict__ widths,
            float* __restrict__ out)
{
    const int tile_x = blockIdx.x;
    const int tile_y = blockIdx.y;
    const int slab   = blockIdx.z;
    const int b      = slab >> 3;
    const int part   = slab & 7;
    const int width  = widths[part];
    const int x0     = tile_x * TX;
    const int y0     = tile_y * TY;          // local row in slab
    const int gy0    = part * HP_ + y0;      // global row

    const int t    = threadIdx.x;
    const int xsub = t & 7;
    const int co   = t >> 3;
    const int xoff = xsub * XS;

    // ---- fast path: whole tile past the valid width -> zeros ----
    if (x0 >= width) {
        const float4 z = make_float4(0.f, 0.f, 0.f, 0.f);
        #pragma unroll
        for (int o = 0; o < TY; ++o) {
            int base = ((b * CO_ + co) * H_ + gy0 + o) * W_ + x0 + xoff;
            *(float4*)(out + base)     = z;
            *(float4*)(out + base + 4) = z;
        }
        return;
    }

    float* sIn = smem;                 // [ci][6][68]

    // ---- stage input tile (masked). Warp w stages ci in [4w, 4w+4).
    //      Compile-time (ci,r) indices, coalesced global reads. ----
    {
        const int warp = t >> 5;
        const int lane = t & 31;
        const int wlim = (width < W_) ? width : W_;
        const int ci0  = warp * 4;
        const float* xb = x + ((size_t)(b * CI_ + ci0) * H_ + part * HP_) * W_;
        float* sb = sIn + ci0 * (SIN_ROWS * SIN_COLS);
        #pragma unroll
        for (int rr = 0; rr < 24; ++rr) {
            const int cio = rr / 6;          // compile-time
            const int r   = rr % 6;          // compile-time
            const int ly  = y0 - 2 + r;      // local row in slab
            const float* grow = xb + (size_t)cio * H_ * W_ + ly * W_;
            float* srow = sb + (cio * SIN_ROWS + r) * SIN_COLS;
            const bool rowok = (ly >= 0) && (ly < HP_);
            int g0 = x0 - 2 + lane;
            int g1 = g0 + 32;
            float v0 = 0.f, v1 = 0.f;
            if (rowok) {
                if (g0 >= 0 && g0 < wlim) v0 = grow[g0];
                if (g1 < wlim)            v1 = grow[g1];
            }
            srow[lane]      = v0;
            srow[lane + 32] = v1;
            if (lane < 4) {
                int g2 = g0 + 64;
                float v2 = (rowok && g2 < wlim) ? grow[g2] : 0.f;
                srow[lane + 64] = v2;
            }
        }
    }
    __syncthreads();

    float acc[TY][XS];
    #pragma unroll
    for (int o = 0; o < TY; ++o)
        #pragma unroll
        for (int j = 0; j < XS; ++j) acc[o][j] = 0.f;

    const float* wbase = g_w + co * WROW;   // + ci*CO_*WROW per channel
    const float* rb    = sIn + xoff;        // + ci*(SIN_ROWS*SIN_COLS)

    float w0[NTAPS], w1[NTAPS];
    load_w(w0, wbase);                      // ci = 0

    // ci-loop unrolled by 2 with alternating weight buffers; each buffer's
    // loads issue one full FMA block (>200 cyc) before first use.
    #pragma unroll 1
    for (int ci = 0; ci < CI_; ci += 2) {
        load_w(w1, wbase + (ci + 1) * (CO_ * WROW));
        fma_block(acc, rb + ci * (SIN_ROWS * SIN_COLS), w0);
        if (ci + 2 < CI_)
            load_w(w0, wbase + (ci + 2) * (CO_ * WROW));
        fma_block(acc, rb + (ci + 1) * (SIN_ROWS * SIN_COLS), w1);
    }

    // ---- epilogue: bias, leaky-ReLU, width mask, vectorized store ----
    const float bz = __ldg(bias  + co);
    const float al = __ldg(alpha + co);
    #pragma unroll
    for (int o = 0; o < TY; ++o) {
        float vals[XS];
        #pragma unroll
        for (int j = 0; j < XS; ++j) {
            float y = acc[o][j] + bz;
            y = (y > 0.f) ? y : al * y;
            int gx = x0 + xoff + j;
            vals[j] = (gx < width) ? y : 0.f;
        }
        int base = ((b * CO_ + co) * H_ + gy0 + o) * W_ + x0 + xoff;
        *(float4*)(out + base)     = make_float4(vals[0], vals[1], vals[2], vals[3]);
        *(float4*)(out + base + 4) = make_float4(vals[4], vals[5], vals[6], vals[7]);
    }
}

// ---------------------------------------------------------------------------
// Launch
// ---------------------------------------------------------------------------
extern "C" void kernel_launch(void* const* d_in, const int* in_sizes, int n_in,
                              void* d_out, int out_size)
{
    const float* x      = (const float*)d_in[0];
    const float* weight = (const float*)d_in[1];
    const float* bias   = (const float*)d_in[2];
    const float* alpha  = (const float*)d_in[3];
    const int*   widths = (const int*)  d_in[4];
    float* out = (float*)d_out;

    (void)in_sizes; (void)n_in; (void)out_size;

    cudaFuncSetAttribute(conv_kernel,
                         cudaFuncAttributeMaxDynamicSharedMemorySize,
                         SMEM_BYTES);

    prep_weights<<<(CI_ * CO_ * WROW + 255) / 256, 256>>>(weight);

    dim3 grid(W_ / TX, HP_ / TY, B_ * NPART);
    conv_kernel<<<grid, NTHREADS, SMEM_BYTES>>>(x, bias, alpha, widths, out);
}

// round 6
// speedup vs baseline: 1.2701x; 1.0582x over previous
#include <cuda_runtime.h>
#include <cuda_bf16.h>

// Problem constants
#define NGROUPS 8
#define CIN 4
#define COUT 4
#define KSIZE 5
#define NPART 8
#define B_    8
#define H_    256
#define W_    512
#define CI_   32
#define CO_   32
#define HP_   32      // H_/NPART rows per slab

// Tile config: 64 cols x 4 rows x 32 co per block.
// Thread = (xsub: 8 cols) x (co-pair: 2 co) x (band: 2 rows) -> 8*16*2 = 256
#define TX 64
#define TY 4
#define XS 8
#define NTHREADS 256

#define NTAPS 13
#define SIN_ROWS 6            // TY + 2
#define SIN_COLS 68           // TX + 4
#define SIN_ELEMS (CI_ * SIN_ROWS * SIN_COLS)       // 13056
#define SMEM_BYTES (SIN_ELEMS * 4)                  // 52224 -> 3 blocks/SM

// Masked-weight scratch in global: layout [ci][co][16] (taps padded 13->16)
#define WROW 16
__device__ float g_w[CI_ * CO_ * WROW];

// ---------------------------------------------------------------------------
// Prep: apply PixelCNN group mask (HIDDEN: center visible iff gin<=gout),
// reorder weights to [ci][co][16taps].
// tap 0..9 -> ky=tap/5, kx=tap%5 ; tap 10,11 -> ky=2,kx=0,1 ; tap 12 -> center
// ---------------------------------------------------------------------------
__global__ void prep_weights(const float* __restrict__ w) {
    int i = blockIdx.x * blockDim.x + threadIdx.x;
    if (i >= CI_ * CO_ * WROW) return;
    int k  = i & 15;
    int co = (i >> 4) & 31;
    int ci = i >> 9;
    float val = 0.0f;
    if (k < NTAPS) {
        int ky, kx;
        float m = 1.0f;
        if (k < 10)      { ky = k / 5; kx = k % 5; }
        else if (k == 10){ ky = 2; kx = 0; }
        else if (k == 11){ ky = 2; kx = 1; }
        else             { ky = 2; kx = 2; m = ((ci >> 2) <= (co >> 2)) ? 1.0f : 0.0f; }
        val = w[((co * CI_ + ci) * KSIZE + ky) * KSIZE + kx] * m;
    }
    g_w[i] = val;
}

__device__ __forceinline__ void load_w(float* wgt, const float* __restrict__ wp) {
    const float4* q = (const float4*)wp;
    float4 a = __ldg(q);
    float4 b = __ldg(q + 1);
    float4 c = __ldg(q + 2);
    wgt[0]=a.x; wgt[1]=a.y; wgt[2]=a.z;  wgt[3]=a.w;
    wgt[4]=b.x; wgt[5]=b.y; wgt[6]=b.z;  wgt[7]=b.w;
    wgt[8]=c.x; wgt[9]=c.y; wgt[10]=c.z; wgt[11]=c.w;
    wgt[12] = __ldg(wp + 12);
}

// ---------------------------------------------------------------------------
// Main conv kernel. Grid: (W/TX=8, HP/TY=8, B*NPART=64). Block: 256 threads.
// ---------------------------------------------------------------------------
extern __shared__ float smem[];

__global__ void __launch_bounds__(NTHREADS, 3)
conv_kernel(const float* __restrict__ x,
            const float* __restrict__ bias,
            const float* __restrict__ alpha,
            const int*   __restrict__ widths,
            float* __restrict__ out)
{
    const int tile_x = blockIdx.x;
    const int tile_y = blockIdx.y;
    const int slab   = blockIdx.z;
    const int b      = slab >> 3;
    const int part   = slab & 7;
    const int width  = widths[part];
    const int x0     = tile_x * TX;
    const int y0     = tile_y * TY;          // local row in slab
    const int gy0    = part * HP_ + y0;      // global row

    const int t    = threadIdx.x;
    const int xsub = t & 7;
    const int cop  = (t >> 3) & 15;
    const int band = t >> 7;                 // 0 or 1
    const int co0  = cop * 2;
    const int xoff = xsub * XS;
    const int r0   = band * 2;               // first out row (local to tile)

    // ---- fast path: whole tile past the valid width -> zeros ----
    if (x0 >= width) {
        const float4 z = make_float4(0.f, 0.f, 0.f, 0.f);
        #pragma unroll
        for (int c = 0; c < 2; ++c)
            #pragma unroll
            for (int o = 0; o < 2; ++o) {
                int base = ((b * CO_ + co0 + c) * H_ + gy0 + r0 + o) * W_ + x0 + xoff;
                *(float4*)(out + base)     = z;
                *(float4*)(out + base + 4) = z;
            }
        return;
    }

    float* sIn = smem;                 // [ci][6][68]

    // ---- stage input tile (masked). Warp w stages ci in [4w, 4w+4). ----
    {
        const int warp = t >> 5;
        const int lane = t & 31;
        const int wlim = (width < W_) ? width : W_;
        const int ci0  = warp * 4;
        const float* xb = x + ((size_t)(b * CI_ + ci0) * H_ + part * HP_) * W_;
        float* sb = sIn + ci0 * (SIN_ROWS * SIN_COLS);
        #pragma unroll
        for (int rr = 0; rr < 24; ++rr) {
            const int cio = rr / 6;          // compile-time
            const int r   = rr % 6;          // compile-time
            const int ly  = y0 - 2 + r;      // local row in slab
            const float* grow = xb + (size_t)cio * H_ * W_ + ly * W_;
            float* srow = sb + (cio * SIN_ROWS + r) * SIN_COLS;
            const bool rowok = (ly >= 0) && (ly < HP_);
            int g0 = x0 - 2 + lane;
            int g1 = g0 + 32;
            float v0 = 0.f, v1 = 0.f;
            if (rowok) {
                if (g0 >= 0 && g0 < wlim) v0 = grow[g0];
                if (g1 < wlim)            v1 = grow[g1];
            }
            srow[lane]      = v0;
            srow[lane + 32] = v1;
            if (lane < 4) {
                int g2 = g0 + 64;
                float v2 = (rowok && g2 < wlim) ? grow[g2] : 0.f;
                srow[lane + 64] = v2;
            }
        }
    }
    __syncthreads();

    // acc[co][row][col]
    float acc[2][2][XS];
    #pragma unroll
    for (int c = 0; c < 2; ++c)
        #pragma unroll
        for (int o = 0; o < 2; ++o)
            #pragma unroll
            for (int j = 0; j < XS; ++j) acc[c][o][j] = 0.f;

    // Thread reads smem rows r0 .. r0+3 (out row oy uses rows oy, oy+1, oy+2)
    const float* rbase = sIn + r0 * SIN_COLS + xoff;

    #pragma unroll 1
    for (int ci = 0; ci < CI_; ++ci) {
        float w0[NTAPS], w1[NTAPS];
        const float* wp = g_w + (ci * CO_ + co0) * WROW;
        load_w(w0, wp);
        load_w(w1, wp + WROW);

        const float* rb = rbase + ci * (SIN_ROWS * SIN_COLS);
        #pragma unroll
        for (int q = 0; q < 4; ++q) {
            float v[12];
            const float4 a0 = *(const float4*)(rb + q * SIN_COLS);
            const float4 a1 = *(const float4*)(rb + q * SIN_COLS + 4);
            const float4 a2 = *(const float4*)(rb + q * SIN_COLS + 8);
            v[0]=a0.x; v[1]=a0.y; v[2]=a0.z; v[3]=a0.w;
            v[4]=a1.x; v[5]=a1.y; v[6]=a1.z; v[7]=a1.w;
            v[8]=a2.x; v[9]=a2.y; v[10]=a2.z; v[11]=a2.w;

            // out row 0 (local r0): ky = q, valid for q = 0,1,2
            if (q < 3) {
                const int nkx = (q == 2) ? 3 : 5;
                const int wb  = 5 * q;          // ky0->0, ky1->5, ky2->10
                #pragma unroll
                for (int kx = 0; kx < 5; ++kx) {
                    if (kx < nkx) {
                        #pragma unroll
                        for (int j = 0; j < XS; ++j) {
                            acc[0][0][j] = fmaf(v[j + kx], w0[wb + kx], acc[0][0][j]);
                            acc[1][0][j] = fmaf(v[j + kx], w1[wb + kx], acc[1][0][j]);
                        }
                    }
                }
            }
            // out row 1 (local r0+1): ky = q-1, valid for q = 1,2,3
            if (q >= 1) {
                const int ky  = q - 1;
                const int nkx = (ky == 2) ? 3 : 5;
                const int wb  = 5 * ky;
                #pragma unroll
                for (int kx = 0; kx < 5; ++kx) {
                    if (kx < nkx) {
                        #pragma unroll
                        for (int j = 0; j < XS; ++j) {
                            acc[0][1][j] = fmaf(v[j + kx], w0[wb + kx], acc[0][1][j]);
                            acc[1][1][j] = fmaf(v[j + kx], w1[wb + kx], acc[1][1][j]);
                        }
                    }
                }
            }
        }
    }

    // ---- epilogue: bias, leaky-ReLU, width mask, vectorized store ----
    #pragma unroll
    for (int c = 0; c < 2; ++c) {
        const float bz = __ldg(bias  + co0 + c);
        const float al = __ldg(alpha + co0 + c);
        #pragma unroll
        for (int o = 0; o < 2; ++o) {
            float vals[XS];
            #pragma unroll
            for (int j = 0; j < XS; ++j) {
                float y = acc[c][o][j] + bz;
                y = (y > 0.f) ? y : al * y;
                int gx = x0 + xoff + j;
                vals[j] = (gx < width) ? y : 0.f;
            }
            int base = ((b * CO_ + co0 + c) * H_ + gy0 + r0 + o) * W_ + x0 + xoff;
            *(float4*)(out + base)     = make_float4(vals[0], vals[1], vals[2], vals[3]);
            *(float4*)(out + base + 4) = make_float4(vals[4], vals[5], vals[6], vals[7]);
        }
    }
}

// ---------------------------------------------------------------------------
// Launch
// ---------------------------------------------------------------------------
extern "C" void kernel_launch(void* const* d_in, const int* in_sizes, int n_in,
                              void* d_out, int out_size)
{
    const float* x      = (const float*)d_in[0];
    const float* weight = (const float*)d_in[1];
    const float* bias   = (const float*)d_in[2];
    const float* alpha  = (const float*)d_in[3];
    const int*   widths = (const int*)  d_in[4];
    float* out = (float*)d_out;

    (void)in_sizes; (void)n_in; (void)out_size;

    cudaFuncSetAttribute(conv_kernel,
                         cudaFuncAttributeMaxDynamicSharedMemorySize,
                         SMEM_BYTES);

    prep_weights<<<(CI_ * CO_ * WROW + 255) / 256, 256>>>(weight);

    dim3 grid(W_ / TX, HP_ / TY, B_ * NPART);
    conv_kernel<<<grid, NTHREADS, SMEM_BYTES>>>(x, bias, alpha, widths, out);
}